// round 9
// baseline (speedup 1.0000x reference)
#include <cuda_runtime.h>

// RMAC: x (64, 2048, 16, 16) f32 -> out (64, 14*2048) f32, L2-normalized rows.
// Separable regions: row-window sums per column first, then column windows.
// Window set (rows and cols): 0:[0,16) 1:[0,10) 2:[4,14) 3:[0,8) 4:[3,11) 5:[6,14)

#define BATCH   64
#define CDIM    2048
#define FEAT    28672           // 14 * 2048
#define TILES   32              // tiles per block (2 per warp, 512-thread blocks)
#define NBLK    4096            // 131072 tiles / 32

__device__ float g_partials[NBLK];   // per-pool-block sum of squares
__device__ float g_inv[BATCH];       // 1 / max(||f_b||, eps)

__constant__ int c_wstart[6] = {0, 0, 4, 0, 3, 6};
__constant__ int c_wlen[6]   = {16, 10, 10, 8, 8, 8};
__constant__ int   c_rw[14]  = {0, 1,1,2,2, 3,3,3,4,4,4,5,5,5};
__constant__ int   c_cw[14]  = {0, 1,2,1,2, 3,4,5,3,4,5,3,4,5};
__constant__ float c_area[14] = {1.0f/256.0f,
                                 0.01f, 0.01f, 0.01f, 0.01f,
                                 1.0f/64.0f, 1.0f/64.0f, 1.0f/64.0f,
                                 1.0f/64.0f, 1.0f/64.0f, 1.0f/64.0f,
                                 1.0f/64.0f, 1.0f/64.0f, 1.0f/64.0f};

__global__ __launch_bounds__(512)
void rmac_pool(const float* __restrict__ x, float* __restrict__ out) {
    // cs[tile][rowwin][col], col-stride 17 floats: conflict-free phase-3 reads
    __shared__ float cs[TILES][6][17];
    __shared__ float red[16];

    const int tid  = threadIdx.x;
    const int lane = tid & 31;
    const int warp = tid >> 5;          // 0..15, handles tiles 2w, 2w+1
    const int col  = lane & 15;
    const bool hi  = lane >= 16;        // hi half handles odd rows

    // Each warp streams two 1KB tiles; every LDG is one contiguous 128B line.
    // 16 independent loads per thread -> deep MLP.
    const float* p = x + (size_t)blockIdx.x * 8192 + warp * 512 + lane;
    float a0 = __ldg(p +   0), a1 = __ldg(p +  32), a2 = __ldg(p +  64),
          a3 = __ldg(p +  96), a4 = __ldg(p + 128), a5 = __ldg(p + 160),
          a6 = __ldg(p + 192), a7 = __ldg(p + 224);
    float b0 = __ldg(p + 256), b1 = __ldg(p + 288), b2 = __ldg(p + 320),
          b3 = __ldg(p + 352), b4 = __ldg(p + 384), b5 = __ldg(p + 416),
          b6 = __ldg(p + 448), b7 = __ldg(p + 480);

    const unsigned m = 0xFFFFFFFFu;
    const int t0 = warp * 2, t1 = warp * 2 + 1;

    // ---- tile 0: row-window sums for this column (lane's 8 rows = 2i+hi) ----
    {
        const float p01 = a0 + a1, p23 = a2 + a3, p45 = a4 + a5, p67 = a6 + a7;
        float w0 = (p01 + p23) + (p45 + p67);         // [0,16)
        float w1 = (p01 + p23) + a4;                  // [0,10)
        float w2 = (p23 + p45) + a6;                  // [4,14)
        float w3 = p01 + p23;                         // [0,8)
        float w5 = (a3 + a4) + (a5 + a6);             // [6,14)
        float w4 = (a2 + a3) + a4 + (hi ? a1 : a5);   // [3,11)
        w0 += __shfl_xor_sync(m, w0, 16);
        w1 += __shfl_xor_sync(m, w1, 16);
        w2 += __shfl_xor_sync(m, w2, 16);
        w3 += __shfl_xor_sync(m, w3, 16);
        w4 += __shfl_xor_sync(m, w4, 16);
        w5 += __shfl_xor_sync(m, w5, 16);
        if (!hi) {
            cs[t0][0][col] = w0; cs[t0][1][col] = w1; cs[t0][2][col] = w2;
            cs[t0][3][col] = w3; cs[t0][4][col] = w4; cs[t0][5][col] = w5;
        }
    }
    // ---- tile 1 ----
    {
        const float p01 = b0 + b1, p23 = b2 + b3, p45 = b4 + b5, p67 = b6 + b7;
        float w0 = (p01 + p23) + (p45 + p67);
        float w1 = (p01 + p23) + b4;
        float w2 = (p23 + p45) + b6;
        float w3 = p01 + p23;
        float w5 = (b3 + b4) + (b5 + b6);
        float w4 = (b2 + b3) + b4 + (hi ? b1 : b5);
        w0 += __shfl_xor_sync(m, w0, 16);
        w1 += __shfl_xor_sync(m, w1, 16);
        w2 += __shfl_xor_sync(m, w2, 16);
        w3 += __shfl_xor_sync(m, w3, 16);
        w4 += __shfl_xor_sync(m, w4, 16);
        w5 += __shfl_xor_sync(m, w5, 16);
        if (!hi) {
            cs[t1][0][col] = w0; cs[t1][1][col] = w1; cs[t1][2][col] = w2;
            cs[t1][3][col] = w3; cs[t1][4][col] = w4; cs[t1][5][col] = w5;
        }
    }

    __syncthreads();

    // Phase 3: 448 threads, one (region, tile) each. Each warp spans 16
    // consecutive tiles of one half -> conflict-free smem, 64B coalesced stores.
    float sq = 0.0f;
    {
        const int half = tid >> 8;         // 0: tiles 0-15, 1: tiles 16-31
        const int sub  = tid & 255;
        if (sub < 224) {
            const int reg = sub >> 4;      // 0..13
            const int t   = (sub & 15) + half * 16;
            const int rw  = c_rw[reg];
            const int cw  = c_cw[reg];
            const int st  = c_wstart[cw];
            const int len = c_wlen[cw];

            float s = 0.0f;
            #pragma unroll 4
            for (int i = 0; i < len; ++i) s += cs[t][rw][st + i];

            const float val = s * c_area[reg];
            const int gt = blockIdx.x * TILES + t;
            const int b  = gt >> 11;
            const int c  = gt & 2047;
            out[(size_t)b * FEAT + reg * CDIM + c] = val;
            sq = val * val;
        }
    }

    // Deterministic block reduction of sum of squares.
    #pragma unroll
    for (int o = 16; o > 0; o >>= 1) sq += __shfl_xor_sync(m, sq, o);
    if (lane == 0) red[warp] = sq;
    __syncthreads();
    if (warp == 0) {
        float t2 = (lane < 16) ? red[lane] : 0.0f;
        #pragma unroll
        for (int o = 8; o > 0; o >>= 1) t2 += __shfl_xor_sync(m, t2, o);
        if (lane == 0) g_partials[blockIdx.x] = t2;
    }
}

// 64 blocks x 64 threads: reduce the 64 partials of each batch -> g_inv[b].
__global__ __launch_bounds__(64)
void rmac_inv() {
    __shared__ float red[2];
    const int b = blockIdx.x, tid = threadIdx.x;
    float s = g_partials[b * 64 + tid];
    #pragma unroll
    for (int o = 16; o > 0; o >>= 1) s += __shfl_xor_sync(0xFFFFFFFFu, s, o);
    if ((tid & 31) == 0) red[tid >> 5] = s;
    __syncthreads();
    if (tid == 0)
        g_inv[b] = 1.0f / fmaxf(sqrtf(red[0] + red[1]), 1e-12f);
}

// grid (28, 64), 256 threads, one float4 each: pure stream after one
// broadcast load of g_inv[b].
__global__ __launch_bounds__(256)
void rmac_scale(float* __restrict__ out) {
    const float inv = __ldg(&g_inv[blockIdx.y]);
    float4* p = (float4*)(out + (size_t)blockIdx.y * FEAT)
              + blockIdx.x * 256 + threadIdx.x;
    float4 v = p[0];
    v.x *= inv; v.y *= inv; v.z *= inv; v.w *= inv;
    p[0] = v;
}

extern "C" void kernel_launch(void* const* d_in, const int* in_sizes, int n_in,
                              void* d_out, int out_size) {
    const float* x = (const float*)d_in[0];
    float* out = (float*)d_out;

    rmac_pool<<<NBLK, 512>>>(x, out);
    rmac_inv<<<BATCH, 64>>>();
    rmac_scale<<<dim3(28, BATCH), 256>>>(out);
}

// round 10
// speedup vs baseline: 1.3154x; 1.3154x over previous
#include <cuda_runtime.h>

// RMAC: x (64, 2048, 16, 16) f32 -> out (64, 14*2048) f32, L2-normalized rows.
// Separable regions: row-window sums per column first, then column windows.
// Window set (rows and cols): 0:[0,16) 1:[0,10) 2:[4,14) 3:[0,8) 4:[3,11) 5:[6,14)

#define BATCH   64
#define CDIM    2048
#define FEAT    28672           // 14 * 2048
#define TILES   16              // one warp per tile, 512-thread blocks
#define NBLK    8192            // 131072 tiles / 16

__device__ float g_partials[NBLK];   // per-pool-block sum of squares

__constant__ int c_wstart[6] = {0, 0, 4, 0, 3, 6};
__constant__ int   c_rw[14]  = {0, 1,1,2,2, 3,3,3,4,4,4,5,5,5};
__constant__ int   c_cw[14]  = {0, 1,2,1,2, 3,4,5,3,4,5,3,4,5};
__constant__ float c_area[14] = {1.0f/256.0f,
                                 0.01f, 0.01f, 0.01f, 0.01f,
                                 1.0f/64.0f, 1.0f/64.0f, 1.0f/64.0f,
                                 1.0f/64.0f, 1.0f/64.0f, 1.0f/64.0f,
                                 1.0f/64.0f, 1.0f/64.0f, 1.0f/64.0f};

__global__ __launch_bounds__(512)
void rmac_pool(const float* __restrict__ x, float* __restrict__ out) {
    // cs[tile][rowwin][half*16 + col]; 33-stride keeps both the phase-1 STS
    // (banks = col+16*hi + const -> 32 distinct) and the phase-3 LDS
    // (banks = 6*t*33 + c = 6t+c mod 32, 16 distinct t) conflict-free.
    __shared__ float cs[TILES][6][33];
    __shared__ float red[16];

    const int tid  = threadIdx.x;
    const int lane = tid & 31;
    const int warp = tid >> 5;          // = tile index, 0..15
    const int col  = lane & 15;
    const bool hi  = lane >= 16;        // hi half handles odd rows

    // Warp streams its 1KB tile; every LDG is one contiguous 128B line.
    // Evict-first: don't let the 134MB x stream evict `out` from L2.
    const float* p = x + (size_t)blockIdx.x * 4096 + warp * 256 + lane;
    float v0 = __ldcs(p +   0);   // row 2*0 + hi
    float v1 = __ldcs(p +  32);
    float v2 = __ldcs(p +  64);
    float v3 = __ldcs(p +  96);
    float v4 = __ldcs(p + 128);
    float v5 = __ldcs(p + 160);
    float v6 = __ldcs(p + 192);
    float v7 = __ldcs(p + 224);

    // Row-window partial sums for this column over this lane's 8 rows (2i+hi).
    const float p01 = v0 + v1, p23 = v2 + v3, p45 = v4 + v5, p67 = v6 + v7;
    const float w0 = (p01 + p23) + (p45 + p67);         // rows [0,16)
    const float w1 = (p01 + p23) + v4;                  // rows [0,10)
    const float w2 = (p23 + p45) + v6;                  // rows [4,14)
    const float w3 = p01 + p23;                         // rows [0,8)
    const float w5 = (v3 + v4) + (v5 + v6);             // rows [6,14)
    const float w4 = (v2 + v3) + v4 + (hi ? v1 : v5);   // rows [3,11)

    // No shuffles: both halves store; phase 3 adds them.
    const int cc = col + (hi ? 16 : 0);
    cs[warp][0][cc] = w0;
    cs[warp][1][cc] = w1;
    cs[warp][2][cc] = w2;
    cs[warp][3][cc] = w3;
    cs[warp][4][cc] = w4;
    cs[warp][5][cc] = w5;

    __syncthreads();

    // Phase 3: 224 threads, one (region, tile) each; t fastest -> 64B stores.
    const unsigned m = 0xFFFFFFFFu;
    float sq = 0.0f;
    if (tid < 224) {
        const int reg = tid >> 4;          // 0..13
        const int t   = tid & 15;
        const float* row = cs[t][c_rw[reg]];

        float s;
        if (reg == 0) {                    // cols [0,16), len 16
            s = 0.0f;
            #pragma unroll
            for (int i = 0; i < 16; ++i) s += row[i] + row[16 + i];
        } else if (reg <= 4) {             // len 10, st 0 or 4
            const int st = (c_cw[reg] == 1) ? 0 : 4;
            s = 0.0f;
            #pragma unroll
            for (int i = 0; i < 10; ++i) s += row[st + i] + row[16 + st + i];
        } else {                           // len 8, st in {0,3,6}
            const int st = c_wstart[c_cw[reg]];
            s = 0.0f;
            #pragma unroll
            for (int i = 0; i < 8; ++i) s += row[st + i] + row[16 + st + i];
        }

        const float val = s * c_area[reg];
        const int gt = blockIdx.x * TILES + t;
        const int b  = gt >> 11;
        const int c  = gt & 2047;
        out[(size_t)b * FEAT + reg * CDIM + c] = val;
        sq = val * val;
    }

    // Deterministic block reduction of sum of squares.
    #pragma unroll
    for (int o = 16; o > 0; o >>= 1) sq += __shfl_xor_sync(m, sq, o);
    if (lane == 0) red[warp] = sq;
    __syncthreads();
    if (warp == 0) {
        float t2 = (lane < 16) ? red[lane] : 0.0f;
        #pragma unroll
        for (int o = 8; o > 0; o >>= 1) t2 += __shfl_xor_sync(m, t2, o);
        if (lane == 0) g_partials[blockIdx.x] = t2;
    }
}

// grid (14, 64), 256 threads. Each block re-reduces its batch's 128 partials
// (deterministic fixed tree, ~512B of L2), then scales its slice in place.
__global__ __launch_bounds__(256)
void rmac_scale(float* __restrict__ out) {
    __shared__ float red[4];
    __shared__ float s_inv;
    const int b = blockIdx.y, tid = threadIdx.x;
    const unsigned m = 0xFFFFFFFFu;

    if (tid < 128) {
        float s = g_partials[b * 128 + tid];
        #pragma unroll
        for (int o = 16; o > 0; o >>= 1) s += __shfl_xor_sync(m, s, o);
        if ((tid & 31) == 0) red[tid >> 5] = s;
    }
    __syncthreads();
    if (tid == 0) {
        float t = (red[0] + red[1]) + (red[2] + red[3]);
        s_inv = 1.0f / fmaxf(sqrtf(t), 1e-12f);
    }
    __syncthreads();
    const float inv = s_inv;

    float4* p = (float4*)(out + (size_t)b * FEAT) + blockIdx.x * 512 + tid;
    float4 a = p[0];
    float4 c = p[256];
    a.x *= inv; a.y *= inv; a.z *= inv; a.w *= inv;
    c.x *= inv; c.y *= inv; c.z *= inv; c.w *= inv;
    p[0]   = a;
    p[256] = c;
}

extern "C" void kernel_launch(void* const* d_in, const int* in_sizes, int n_in,
                              void* d_out, int out_size) {
    const float* x = (const float*)d_in[0];
    float* out = (float*)d_out;

    rmac_pool<<<NBLK, 512>>>(x, out);
    rmac_scale<<<dim3(14, BATCH), 256>>>(out);
}